// round 14
// baseline (speedup 1.0000x reference)
#include <cuda_runtime.h>
#include <cuda_bf16.h>
#include <cstdint>

#define N_NODES 500000
#define CUTOFF 5.0f
#define INV_CUTOFF (1.0f / 5.0f)
#define COULOMB_K 14.3996454784936f
// 1/sqrt(2) handled inside rsqrt of 2*(s1^2+s2^2)

// Packed node table: {charge, sigma} — static device alloc (no cudaMalloc).
__device__ float2 g_node[N_NODES];

__global__ void pack_and_zero_kernel(const float* __restrict__ charge,
                                     const float* __restrict__ sigma,
                                     float* __restrict__ out, int n) {
    int i = blockIdx.x * blockDim.x + threadIdx.x;
    if (i < n) {
        g_node[i] = make_float2(charge[i], sigma[i]);
        out[i] = 0.0f;
    }
}

__device__ __forceinline__ void edge_msg(float r, int s, int d,
                                         float* __restrict__ out) {
    float2 nd = __ldg(&g_node[d]);   // {charge[dst], sigma[dst]}
    float  ss = __ldg(&g_node[s]).y; // sigma[src]
    float q_dst = nd.x;
    float sd = nd.y;

    // arg = r / (sqrt2 * sqrt(ss^2 + sd^2)) = r * rsqrt(2*(ss^2+sd^2))
    float denom2 = 2.0f * fmaf(ss, ss, sd * sd);
    float arg = r * rsqrtf(denom2);

    // polynomial cutoff: 1 - 6x^5 + 15x^4 - 10x^3, x = r/cutoff
    float x = r * INV_CUTOFF;
    // f = 1 + x^3*(-10 + 15x - 6x^2)
    float p = fmaf(-6.0f, x, 15.0f);   // 15 - 6x
    p = fmaf(p, x, -10.0f);            // -10 + 15x - 6x^2
    float x3 = x * x * x;
    float fcut = fmaf(x3, p, 1.0f);
    fcut = (r <= CUTOFF) ? fcut : 0.0f;

    float msg = q_dst * erff(arg) * fcut * __fdividef(COULOMB_K, r);
    atomicAdd(&out[d], msg);
}

__global__ void __launch_bounds__(256)
edge_kernel_vec4(const float* __restrict__ bond_dist,
                 const int*   __restrict__ src,
                 const int*   __restrict__ dst,
                 float*       __restrict__ out,
                 int n_edges4) {
    int i = blockIdx.x * blockDim.x + threadIdx.x;
    if (i >= n_edges4) return;

    float4 r4 = reinterpret_cast<const float4*>(bond_dist)[i];
    int4   s4 = reinterpret_cast<const int4*>(src)[i];
    int4   d4 = reinterpret_cast<const int4*>(dst)[i];

    edge_msg(r4.x, s4.x, d4.x, out);
    edge_msg(r4.y, s4.y, d4.y, out);
    edge_msg(r4.z, s4.z, d4.z, out);
    edge_msg(r4.w, s4.w, d4.w, out);
}

__global__ void edge_kernel_tail(const float* __restrict__ bond_dist,
                                 const int*   __restrict__ src,
                                 const int*   __restrict__ dst,
                                 float*       __restrict__ out,
                                 int start, int n_edges) {
    int i = start + blockIdx.x * blockDim.x + threadIdx.x;
    if (i < n_edges) {
        edge_msg(bond_dist[i], src[i], dst[i], out);
    }
}

extern "C" void kernel_launch(void* const* d_in, const int* in_sizes, int n_in,
                              void* d_out, int out_size) {
    // metadata order: charge, sigma, bond_dist, src, dst
    const float* charge    = (const float*)d_in[0];
    const float* sigma     = (const float*)d_in[1];
    const float* bond_dist = (const float*)d_in[2];
    const int*   src       = (const int*)d_in[3];
    const int*   dst       = (const int*)d_in[4];
    float* out = (float*)d_out;

    int n_nodes = in_sizes[0];
    int n_edges = in_sizes[2];

    {
        int threads = 256;
        int blocks = (n_nodes + threads - 1) / threads;
        pack_and_zero_kernel<<<blocks, threads>>>(charge, sigma, out, n_nodes);
    }

    int n4 = n_edges / 4;
    if (n4 > 0) {
        int threads = 256;
        int blocks = (n4 + threads - 1) / threads;
        edge_kernel_vec4<<<blocks, threads>>>(bond_dist, src, dst, out, n4);
    }
    int tail_start = n4 * 4;
    int tail = n_edges - tail_start;
    if (tail > 0) {
        edge_kernel_tail<<<1, 256>>>(bond_dist, src, dst, out, tail_start, n_edges);
    }
}

// round 15
// speedup vs baseline: 1.0158x; 1.0158x over previous
#include <cuda_runtime.h>
#include <cuda_bf16.h>
#include <cstdint>

#define N_NODES 500000
#define CUTOFF 5.0f
#define INV_CUTOFF (1.0f / 5.0f)
#define COULOMB_K 14.3996454784936f
// 1/sqrt(2) handled inside rsqrt of 2*(s1^2+s2^2)

// Packed node table: {charge, sigma} — static device alloc (no cudaMalloc).
__device__ float2 g_node[N_NODES];

__global__ void pack_and_zero_kernel(const float* __restrict__ charge,
                                     const float* __restrict__ sigma,
                                     float* __restrict__ out, int n) {
    int i = blockIdx.x * blockDim.x + threadIdx.x;
    if (i < n) {
        g_node[i] = make_float2(charge[i], sigma[i]);
        out[i] = 0.0f;
    }
}

__device__ __forceinline__ void edge_msg(float r, int s, int d,
                                         float* __restrict__ out) {
    float2 nd = __ldg(&g_node[d]);   // {charge[dst], sigma[dst]} — one 8B gather
    float  ss = __ldg(&g_node[s]).y; // sigma[src]
    float q_dst = nd.x;
    float sd = nd.y;

    // arg = r / (sqrt2 * sqrt(ss^2 + sd^2)) = r * rsqrt(2*(ss^2+sd^2))
    float denom2 = 2.0f * fmaf(ss, ss, sd * sd);
    float arg = r * rsqrtf(denom2);

    // polynomial cutoff: 1 - 6x^5 + 15x^4 - 10x^3, x = r/cutoff
    float x = r * INV_CUTOFF;
    // f = 1 + x^3*(-10 + 15x - 6x^2)
    float p = fmaf(-6.0f, x, 15.0f);   // 15 - 6x
    p = fmaf(p, x, -10.0f);            // -10 + 15x - 6x^2
    float x3 = x * x * x;
    float fcut = fmaf(x3, p, 1.0f);
    fcut = (r <= CUTOFF) ? fcut : 0.0f;

    float msg = q_dst * erff(arg) * fcut * __fdividef(COULOMB_K, r);
    atomicAdd(&out[d], msg);           // RED.ADD.F32 (no return)
}

__global__ void __launch_bounds__(256)
edge_kernel_vec4(const float* __restrict__ bond_dist,
                 const int*   __restrict__ src,
                 const int*   __restrict__ dst,
                 float*       __restrict__ out,
                 int n_edges4) {
    int i = blockIdx.x * blockDim.x + threadIdx.x;
    if (i >= n_edges4) return;

    float4 r4 = reinterpret_cast<const float4*>(bond_dist)[i];
    int4   s4 = reinterpret_cast<const int4*>(src)[i];
    int4   d4 = reinterpret_cast<const int4*>(dst)[i];

    edge_msg(r4.x, s4.x, d4.x, out);
    edge_msg(r4.y, s4.y, d4.y, out);
    edge_msg(r4.z, s4.z, d4.z, out);
    edge_msg(r4.w, s4.w, d4.w, out);
}

__global__ void edge_kernel_tail(const float* __restrict__ bond_dist,
                                 const int*   __restrict__ src,
                                 const int*   __restrict__ dst,
                                 float*       __restrict__ out,
                                 int start, int n_edges) {
    int i = start + blockIdx.x * blockDim.x + threadIdx.x;
    if (i < n_edges) {
        edge_msg(bond_dist[i], src[i], dst[i], out);
    }
}

extern "C" void kernel_launch(void* const* d_in, const int* in_sizes, int n_in,
                              void* d_out, int out_size) {
    // metadata order: charge, sigma, bond_dist, src, dst
    const float* charge    = (const float*)d_in[0];
    const float* sigma     = (const float*)d_in[1];
    const float* bond_dist = (const float*)d_in[2];
    const int*   src       = (const int*)d_in[3];
    const int*   dst       = (const int*)d_in[4];
    float* out = (float*)d_out;

    int n_nodes = in_sizes[0];
    int n_edges = in_sizes[2];

    {
        int threads = 256;
        int blocks = (n_nodes + threads - 1) / threads;
        pack_and_zero_kernel<<<blocks, threads>>>(charge, sigma, out, n_nodes);
    }

    int n4 = n_edges / 4;
    if (n4 > 0) {
        int threads = 256;
        int blocks = (n4 + threads - 1) / threads;
        edge_kernel_vec4<<<blocks, threads>>>(bond_dist, src, dst, out, n4);
    }
    int tail_start = n4 * 4;
    int tail = n_edges - tail_start;
    if (tail > 0) {
        edge_kernel_tail<<<1, 256>>>(bond_dist, src, dst, out, tail_start, n_edges);
    }
}